// round 5
// baseline (speedup 1.0000x reference)
#include <cuda_runtime.h>
#include <cuda_bf16.h>
#include <cstdint>
#include <math.h>

// ---------------------------------------------------------------------------
// Problem constants
#define BB 2048
#define NN 50000
#define CC 768
#define TK 16
#define NCAND 32
#define NPARTS 37
#define NT 11                 // 128-col tiles per part
#define PSPAN (NT*128)        // 1408
#define NPAD (NPARTS*PSPAN)   // 52096
#define NLISTS NPARTS         // 37 partial lists per row (merged in-CTA)
#define NEG_INF __int_as_float(0xff800000)

// Scratch (device globals: no cudaMalloc allowed)
__device__ __nv_bfloat16 g_Ebf[(size_t)NPAD * CC];   // row-scaled by 1/||e||
__device__ __nv_bfloat16 g_Xbf[(size_t)BB * CC];
__device__ float  g_pvals[(size_t)BB * NLISTS * TK];
__device__ int    g_pidx [(size_t)BB * NLISTS * TK];
__device__ int    g_cand [(size_t)BB * NCAND];
__device__ double g_csim [(size_t)BB * NCAND];
__device__ int    g_fidx [(size_t)BB * TK];

// ---------------------------------------------------------------------------
// Baseline-PTX helpers (NO sm_103a-gated instructions)
// ---------------------------------------------------------------------------
__device__ __forceinline__ uint32_t smem_u32(const void* p) {
    uint32_t a;
    asm("{ .reg .u64 t; cvta.to.shared.u64 t, %1; cvt.u32.u64 %0, t; }" : "=r"(a) : "l"(p));
    return a;
}
__device__ __forceinline__ void cp16(uint32_t saddr, const void* g) {
    asm volatile("cp.async.cg.shared.global [%0], [%1], 16;" :: "r"(saddr), "l"(g));
}
#define CP_COMMIT() asm volatile("cp.async.commit_group;" ::: "memory")
#define CP_WAIT2()  asm volatile("cp.async.wait_group 2;" ::: "memory")

__device__ __forceinline__ void ldm_x4(uint32_t& r0, uint32_t& r1, uint32_t& r2,
                                       uint32_t& r3, uint32_t a) {
    asm volatile("ldmatrix.sync.aligned.m8n8.x4.shared.b16 {%0,%1,%2,%3}, [%4];"
                 : "=r"(r0), "=r"(r1), "=r"(r2), "=r"(r3) : "r"(a));
}
__device__ __forceinline__ void mma16816(float* c, const uint32_t* a, const uint32_t* b) {
    asm volatile(
        "mma.sync.aligned.m16n8k16.row.col.f32.bf16.bf16.f32 "
        "{%0,%1,%2,%3}, {%4,%5,%6,%7}, {%8,%9}, {%0,%1,%2,%3};"
        : "+f"(c[0]), "+f"(c[1]), "+f"(c[2]), "+f"(c[3])
        : "r"(a[0]), "r"(a[1]), "r"(a[2]), "r"(a[3]), "r"(b[0]), "r"(b[1]));
}
__device__ __forceinline__ uint32_t swz(uint32_t off) { return off ^ ((off >> 3) & 0x70); }

// ---------------------------------------------------------------------------
// Prepass: E -> bf16 scaled by 1/||e|| (rows >= NN zeroed); X -> bf16
// ---------------------------------------------------------------------------
__global__ void prepE_kernel(const float* __restrict__ E) {
    int w = (blockIdx.x * blockDim.x + threadIdx.x) >> 5;
    int lane = threadIdx.x & 31;
    if (w >= NPAD) return;
    uint32_t* orow = reinterpret_cast<uint32_t*>(g_Ebf + (size_t)w * CC);
    if (w >= NN) {
        #pragma unroll
        for (int i = 0; i < 6; i++) { orow[(lane+32*i)*2] = 0u; orow[(lane+32*i)*2+1] = 0u; }
        return;
    }
    const float4* r4 = reinterpret_cast<const float4*>(E + (size_t)w * CC);
    float s = 0.f;
    float4 v[6];
    #pragma unroll
    for (int i = 0; i < 6; i++) {
        v[i] = r4[lane + 32*i];
        s += v[i].x*v[i].x + v[i].y*v[i].y + v[i].z*v[i].z + v[i].w*v[i].w;
    }
    #pragma unroll
    for (int o = 16; o; o >>= 1) s += __shfl_xor_sync(0xffffffffu, s, o);
    float inv = rsqrtf(s);
    #pragma unroll
    for (int i = 0; i < 6; i++) {
        __nv_bfloat162 h0 = __floats2bfloat162_rn(v[i].x*inv, v[i].y*inv);
        __nv_bfloat162 h1 = __floats2bfloat162_rn(v[i].z*inv, v[i].w*inv);
        orow[(lane+32*i)*2]   = *reinterpret_cast<uint32_t*>(&h0);
        orow[(lane+32*i)*2+1] = *reinterpret_cast<uint32_t*>(&h1);
    }
}

__global__ void prepX_kernel(const float* __restrict__ X) {
    int w = (blockIdx.x * blockDim.x + threadIdx.x) >> 5;
    int lane = threadIdx.x & 31;
    if (w >= BB) return;
    const float4* r4 = reinterpret_cast<const float4*>(X + (size_t)w * CC);
    uint32_t* orow = reinterpret_cast<uint32_t*>(g_Xbf + (size_t)w * CC);
    #pragma unroll
    for (int i = 0; i < 6; i++) {
        float4 v = r4[lane + 32*i];
        __nv_bfloat162 h0 = __floats2bfloat162_rn(v.x, v.y);
        __nv_bfloat162 h1 = __floats2bfloat162_rn(v.z, v.w);
        orow[(lane+32*i)*2]   = *reinterpret_cast<uint32_t*>(&h0);
        orow[(lane+32*i)*2+1] = *reinterpret_cast<uint32_t*>(&h1);
    }
}

// ---------------------------------------------------------------------------
// Kernel 1: bf16 HMMA GEMM (mma.sync m16n8k16) + streaming per-row top-16.
// 128x128 CTA tile, 16 warps (4M x 4N), warp tile 32x32, K-chunk 64.
// 4-stage cp.async ring (3 in flight), ONE syncthreads per chunk.
// grid(16 Mblk, 37 parts), 512 threads.
// ---------------------------------------------------------------------------
#define NSTAGE      4
#define STAGE_BYTES 32768              // A 16KB + B 16KB
#define SC_OFF      (NSTAGE*STAGE_BYTES)   // 131072
#define SC_PITCH    133
#define GSMEM       (SC_OFF + 128*SC_PITCH*4)   // 199,168 B

__global__ void __launch_bounds__(512, 1) gemm_topk_kernel() {
    extern __shared__ char sm[];
    const uint32_t smb = smem_u32(sm);
    float* scores = reinterpret_cast<float*>(sm + SC_OFF);

    const int tid  = threadIdx.x;
    const int warp = tid >> 5;
    const int lane = tid & 31;
    const int m0   = blockIdx.x * 128;
    const int part = blockIdx.y;
    const int pbase = part * PSPAN;

    const int wm = warp >> 2;       // 4 M-warps (32 rows each)
    const int wn = warp & 3;        // 4 N-warps (32 cols each)

    const int NCHUNK = NT * 12;     // 132

    // issue one 32KB stage (A chunk + B chunk) via cp.async; always commits
    auto issue = [&](int ci) {
        if (ci < NCHUNK) {
            const int t = ci / 12, c = ci % 12;
            const uint32_t as = smb + (ci & (NSTAGE - 1)) * STAGE_BYTES;
            const uint32_t bs = as + 16384;
            const __nv_bfloat16* Ab = g_Xbf + (size_t)m0 * CC + c * 64;
            const __nv_bfloat16* Bb = g_Ebf + (size_t)(pbase + t * 128) * CC + c * 64;
            #pragma unroll
            for (int s = 0; s < 2; s++) {
                int u = tid + 512 * s;          // 0..1023
                int row = u >> 3, seg = u & 7;
                cp16(as + swz(row * 128 + seg * 16), Ab + (size_t)row * CC + seg * 8);
                cp16(bs + swz(row * 128 + seg * 16), Bb + (size_t)row * CC + seg * 8);
            }
        }
        CP_COMMIT();   // empty group during drain keeps wait_group counting valid
    };

    // per-(row,half) streaming top-16 (threads 0..255: row=tid&127, half=tid>>7)
    float tvv[TK]; int tii[TK];
    #pragma unroll
    for (int q = 0; q < TK; q++) { tvv[q] = NEG_INF; tii[q] = 0x7fffffff; }
    float mv = NEG_INF; int mp = 0;

    float acc[2][4][4];
    #pragma unroll
    for (int i = 0; i < 2; i++)
        #pragma unroll
        for (int j = 0; j < 4; j++)
            #pragma unroll
            for (int r = 0; r < 4; r++) acc[i][j][r] = 0.f;

    // precomputed ldmatrix lane-address components
    const int a_row = (lane & 15);
    const int a_kh  = (lane >> 4) & 1;
    const int b_nrw = ((lane >> 4) & 1) * 8 + (lane & 7);
    const int b_kh  = (lane >> 3) & 1;

    issue(0); issue(1); issue(2);

    for (int ci = 0; ci < NCHUNK; ci++) {
        CP_WAIT2();          // chunk ci resident (<=2 younger groups outstanding)
        __syncthreads();     // all warps see stage data; all done with ci-1's stage
        issue(ci + 3);       // safe: overwrites stage of chunk ci-1

        // compute chunk ci from stage ci % 4
        {
            const uint32_t as = smb + (ci & (NSTAGE - 1)) * STAGE_BYTES;
            const uint32_t bs = as + 16384;
            #pragma unroll
            for (int ks = 0; ks < 4; ks++) {
                uint32_t a[2][4], b[2][4];
                #pragma unroll
                for (int i = 0; i < 2; i++) {
                    uint32_t off = (uint32_t)(wm * 32 + i * 16 + a_row) * 128
                                 + ks * 32 + a_kh * 16;
                    ldm_x4(a[i][0], a[i][1], a[i][2], a[i][3], as + swz(off));
                }
                #pragma unroll
                for (int j16 = 0; j16 < 2; j16++) {
                    uint32_t off = (uint32_t)(wn * 32 + j16 * 16 + b_nrw) * 128
                                 + ks * 32 + b_kh * 16;
                    ldm_x4(b[j16][0], b[j16][1], b[j16][2], b[j16][3], bs + swz(off));
                }
                #pragma unroll
                for (int i = 0; i < 2; i++)
                    #pragma unroll
                    for (int j2 = 0; j2 < 4; j2++)
                        mma16816(acc[i][j2], a[i], &b[j2 >> 1][(j2 & 1) * 2]);
            }
        }

        if ((ci % 12) == 11) {
            // tile epilogue: stage scores then scan
            const int t = ci / 12;
            const int n0 = pbase + t * 128;
            __syncthreads();   // previous scan fully done (scores region reuse)
            #pragma unroll
            for (int i = 0; i < 2; i++) {
                int row = wm * 32 + i * 16 + (lane >> 2);
                #pragma unroll
                for (int j2 = 0; j2 < 4; j2++) {
                    int col = wn * 32 + j2 * 8 + (lane & 3) * 2;
                    scores[row * SC_PITCH + col]           = acc[i][j2][0];
                    scores[row * SC_PITCH + col + 1]       = acc[i][j2][1];
                    scores[(row + 8) * SC_PITCH + col]     = acc[i][j2][2];
                    scores[(row + 8) * SC_PITCH + col + 1] = acc[i][j2][3];
                    acc[i][j2][0] = 0.f; acc[i][j2][1] = 0.f;
                    acc[i][j2][2] = 0.f; acc[i][j2][3] = 0.f;
                }
            }
            __syncthreads();
            if (tid < 256) {
                const int r    = tid & 127;
                const int half = tid >> 7;
                const float* srow = scores + r * SC_PITCH + half * 64;
                for (int c2 = 0; c2 < 64; c2++) {
                    int n = n0 + half * 64 + c2;
                    float s = srow[c2];
                    if (n < NN && s > mv) {
                        #pragma unroll
                        for (int q = 0; q < TK; q++)
                            if (q == mp) { tvv[q] = s; tii[q] = n; }
                        mv = tvv[0]; mp = 0; int mi = tii[0];
                        #pragma unroll
                        for (int q = 1; q < TK; q++) {
                            if (tvv[q] < mv || (tvv[q] == mv && tii[q] > mi)) {
                                mv = tvv[q]; mp = q; mi = tii[q];
                            }
                        }
                    }
                }
            }
        }
    }

    // in-CTA merge of the two half-lists per row -> one top-16 list per part
    __syncthreads();
    float* fv = scores;                     // [256][16] values
    int*   fi = (int*)(scores + 4096);      // [256][16] indices
    if (tid < 256) {
        const int slot = ((tid >> 7) * 128 + (tid & 127)) * 16;
        #pragma unroll
        for (int q = 0; q < TK; q++) { fv[slot + q] = tvv[q]; fi[slot + q] = tii[q]; }
    }
    __syncthreads();
    if (tid < 128) {
        const int b0 = tid * 16;
        const int b1 = (128 + tid) * 16;
        const size_t base = ((size_t)(m0 + tid) * NLISTS + part) * TK;
        for (int rnd = 0; rnd < TK; rnd++) {
            float bv = NEG_INF; int bi = 0x7fffffff; int bslot = -1;
            #pragma unroll
            for (int q = 0; q < TK; q++) {
                float v0 = fv[b0 + q]; int i0 = fi[b0 + q];
                if (v0 > bv || (v0 == bv && i0 < bi)) { bv = v0; bi = i0; bslot = b0 + q; }
                float v1 = fv[b1 + q]; int i1 = fi[b1 + q];
                if (v1 > bv || (v1 == bv && i1 < bi)) { bv = v1; bi = i1; bslot = b1 + q; }
            }
            if (bslot >= 0) { fv[bslot] = NEG_INF; fi[bslot] = 0x7fffffff; }
            g_pvals[base + rnd] = bv;
            g_pidx [base + rnd] = bi;
        }
    }
}

// ---------------------------------------------------------------------------
// Kernel 2: merge 37x16 partials -> top-32 candidate pool per row (warp/row)
// ---------------------------------------------------------------------------
__global__ void merge_kernel() {
    const int warp = threadIdx.x >> 5;
    const int lane = threadIdx.x & 31;
    const int row  = blockIdx.x * 8 + warp;
    if (row >= BB) return;

    const int NC = NLISTS * TK;     // 592
    const int T = (NC + 31) / 32;   // 19
    float lv[T]; int li[T];
    #pragma unroll
    for (int t = 0; t < T; t++) {
        int g = lane + t * 32;
        if (g < NC) {
            lv[t] = g_pvals[(size_t)row * NC + g];
            li[t] = g_pidx [(size_t)row * NC + g];
        } else { lv[t] = NEG_INF; li[t] = 0x7fffffff; }
    }
    for (int rnd = 0; rnd < NCAND; rnd++) {
        float bv = NEG_INF; int bi = 0x7fffffff; int bs = -1;
        #pragma unroll
        for (int t = 0; t < T; t++)
            if (lv[t] > bv || (lv[t] == bv && li[t] < bi)) { bv = lv[t]; bi = li[t]; bs = t; }
        float wv = bv; int wi = bi;
        #pragma unroll
        for (int o = 16; o; o >>= 1) {
            float ov = __shfl_xor_sync(0xffffffffu, wv, o);
            int   oi = __shfl_xor_sync(0xffffffffu, wi, o);
            if (ov > wv || (ov == wv && oi < wi)) { wv = ov; wi = oi; }
        }
        if (bs >= 0 && bv == wv && bi == wi) { lv[bs] = NEG_INF; li[bs] = 0x7fffffff; }
        if (lane == 0) g_cand[row * NCAND + rnd] = wi;
    }
}

// ---------------------------------------------------------------------------
// Kernel 2.5a: fp64 exact sims — one WARP per (row, candidate)
// ---------------------------------------------------------------------------
__global__ void refine_dot_kernel(const float* __restrict__ X, const float* __restrict__ E) {
    const int gw   = blockIdx.x * 8 + (threadIdx.x >> 5);
    const int lane = threadIdx.x & 31;
    const int row  = gw >> 5;
    const int slot = gw & 31;
    if (row >= BB) return;
    const int cand = g_cand[row * NCAND + slot];
    const float4* x4 = reinterpret_cast<const float4*>(X + (size_t)row  * CC);
    const float4* e4 = reinterpret_cast<const float4*>(E + (size_t)cand * CC);

    double dot = 0.0, e2 = 0.0;
    #pragma unroll
    for (int i = 0; i < 6; i++) {
        float4 xv = x4[lane + 32 * i];
        float4 ev = e4[lane + 32 * i];
        dot = fma((double)xv.x, (double)ev.x, dot);
        e2  = fma((double)ev.x, (double)ev.x, e2);
        dot = fma((double)xv.y, (double)ev.y, dot);
        e2  = fma((double)ev.y, (double)ev.y, e2);
        dot = fma((double)xv.z, (double)ev.z, dot);
        e2  = fma((double)ev.z, (double)ev.z, e2);
        dot = fma((double)xv.w, (double)ev.w, dot);
        e2  = fma((double)ev.w, (double)ev.w, e2);
    }
    #pragma unroll
    for (int o = 16; o; o >>= 1) {
        dot += __shfl_xor_sync(0xffffffffu, dot, o);
        e2  += __shfl_xor_sync(0xffffffffu, e2,  o);
    }
    if (lane == 0) g_csim[row * NCAND + slot] = dot / sqrt(e2);
}

// Kernel 2.5b: sorted top-16 of the 32 exact sims (warp per row)
__global__ void refine_select_kernel() {
    const int warp = threadIdx.x >> 5;
    const int lane = threadIdx.x & 31;
    const int row  = blockIdx.x * 8 + warp;
    if (row >= BB) return;

    double v = g_csim[row * NCAND + lane];
    int  idx = g_cand[row * NCAND + lane];
    for (int rnd = 0; rnd < TK; rnd++) {
        double wv = v; int wi = idx;
        #pragma unroll
        for (int o = 16; o; o >>= 1) {
            double ov = __shfl_xor_sync(0xffffffffu, wv, o);
            int    oi = __shfl_xor_sync(0xffffffffu, wi, o);
            if (ov > wv || (ov == wv && oi < wi)) { wv = ov; wi = oi; }
        }
        if (idx == wi) { v = -INFINITY; idx = 0x7fffffff; }
        if (lane == 0) g_fidx[row * TK + rnd] = wi;
    }
}

// ---------------------------------------------------------------------------
// Kernel 3: gather with reference's reshape(-1,B,C).transpose(1,0,2) scramble
// ---------------------------------------------------------------------------
__global__ void gather_kernel(const float* __restrict__ E, float* __restrict__ out) {
    const int bj = blockIdx.x;        // b*16 + j
    const int b = bj >> 4, j = bj & 15;
    const int src_row  = j * (BB / TK) + (b >> 4);
    const int src_slot = b & 15;
    const int src = g_fidx[src_row * TK + src_slot];
    const float4* s4 = reinterpret_cast<const float4*>(E + (size_t)src * CC);
    float4* d4 = reinterpret_cast<float4*>(out + (size_t)bj * CC);
    d4[threadIdx.x] = s4[threadIdx.x];
}

// ---------------------------------------------------------------------------
extern "C" void kernel_launch(void* const* d_in, const int* in_sizes, int n_in,
                              void* d_out, int out_size) {
    const float* X = (const float*)d_in[0];
    const float* E = (const float*)d_in[1];
    float* out = (float*)d_out;
    (void)in_sizes; (void)n_in; (void)out_size;

    cudaFuncSetAttribute(gemm_topk_kernel,
                         cudaFuncAttributeMaxDynamicSharedMemorySize, GSMEM);

    prepE_kernel<<<NPAD / 8, 256>>>(E);
    prepX_kernel<<<BB / 8, 256>>>(X);
    gemm_topk_kernel<<<dim3(16, NPARTS), 512, GSMEM>>>();
    merge_kernel<<<BB / 8, 256>>>();
    refine_dot_kernel<<<BB * NCAND / 8, 256>>>(X, E);
    refine_select_kernel<<<BB / 8, 256>>>();
    gather_kernel<<<BB * TK, 192>>>(E, out);
}